// round 1
// baseline (speedup 1.0000x reference)
#include <cuda_runtime.h>
#include <math.h>

// Problem constants
#define DM   1024
#define BATCH 8
#define SEQ  2048
#define NH   16
#define HD   64
#define MTOT (BATCH * SEQ)   // 16384 tokens

// Scratch: q/k/v projections (3 x 16384 x 1024 floats = 201MB) + scrambled concat (64MB)
__device__ float g_proj[3u * MTOT * DM];
__device__ float g_concat[(size_t)MTOT * DM];

// ---------------------------------------------------------------------------
// Classic SIMT SGEMM tile: C[128 x 128] = A[128 x 1024] @ W^T + bias
//   A: row-major, ld = 1024 (points at first row of this block)
//   W: row-major [1024][1024]; we compute C[r][n] = sum_k A[r][k] * W[n][k]
//   C: row-major, ld = 1024 (points at first row of this block's output)
// 256 threads, BM=BN=128, BK=16, 8x8 register tile per thread.
// ---------------------------------------------------------------------------
__device__ __forceinline__ void gemm_block(const float* __restrict__ A,
                                           const float* __restrict__ W,
                                           const float* __restrict__ bias,
                                           float* __restrict__ C,
                                           int bn)
{
    __shared__ float As[16][128];
    __shared__ float Bs[16][128];

    const int tid = threadIdx.x;
    const int tx  = tid & 15;   // 0..15 -> column group
    const int ty  = tid >> 4;   // 0..15 -> row group
    const int n0  = bn * 128;

    float acc[8][8];
#pragma unroll
    for (int i = 0; i < 8; ++i)
#pragma unroll
        for (int j = 0; j < 8; ++j) acc[i][j] = 0.f;

    for (int k0 = 0; k0 < DM; k0 += 16) {
        // Load A tile (128x16) and W tile (128x16), both transposed into smem.
#pragma unroll
        for (int l = 0; l < 2; ++l) {
            int idx = tid + l * 256;        // 0..511
            int r   = idx >> 2;             // 0..127
            int c   = (idx & 3) << 2;       // 0,4,8,12
            float4 va = *reinterpret_cast<const float4*>(A + (size_t)r * DM + k0 + c);
            As[c + 0][r] = va.x; As[c + 1][r] = va.y;
            As[c + 2][r] = va.z; As[c + 3][r] = va.w;
            float4 vb = *reinterpret_cast<const float4*>(W + (size_t)(n0 + r) * DM + k0 + c);
            Bs[c + 0][r] = vb.x; Bs[c + 1][r] = vb.y;
            Bs[c + 2][r] = vb.z; Bs[c + 3][r] = vb.w;
        }
        __syncthreads();

#pragma unroll
        for (int k = 0; k < 16; ++k) {
            float a[8], b[8];
#pragma unroll
            for (int i = 0; i < 4; ++i) {
                a[i]     = As[k][ty * 8 + i];
                a[i + 4] = As[k][ty * 8 + 4 + i];
                b[i]     = Bs[k][tx * 8 + i];
                b[i + 4] = Bs[k][tx * 8 + 4 + i];
            }
#pragma unroll
            for (int i = 0; i < 8; ++i)
#pragma unroll
                for (int j = 0; j < 8; ++j)
                    acc[i][j] += a[i] * b[j];
        }
        __syncthreads();
    }

    // Epilogue: add bias, vectorized store
#pragma unroll
    for (int i = 0; i < 8; ++i) {
        int r = ty * 8 + i;
#pragma unroll
        for (int j = 0; j < 8; j += 4) {
            int c = n0 + tx * 8 + j;
            float4 v;
            v.x = acc[i][j + 0] + bias[c + 0];
            v.y = acc[i][j + 1] + bias[c + 1];
            v.z = acc[i][j + 2] + bias[c + 2];
            v.w = acc[i][j + 3] + bias[c + 3];
            *reinterpret_cast<float4*>(C + (size_t)r * DM + c) = v;
        }
    }
}

// Projection GEMM: stacks q,k,v as one M=49152 GEMM. grid = (8, 384)
__global__ __launch_bounds__(256)
void proj_kernel(const float* __restrict__ q, const float* __restrict__ k,
                 const float* __restrict__ v, const float* __restrict__ W,
                 const float* __restrict__ bias)
{
    const int bm  = blockIdx.y;        // 0..383
    const int sel = bm >> 7;           // 0:q 1:k 2:v
    const float* A = (sel == 0) ? q : ((sel == 1) ? k : v);
    const int rowblk = bm & 127;
    const float* Ablk = A + (size_t)rowblk * 128 * DM;
    float* Cblk = g_proj + ((size_t)sel * MTOT + (size_t)rowblk * 128) * DM;
    gemm_block(Ablk, W, bias, Cblk, blockIdx.x);
}

// Final GEMM: out = concat @ W^T + bias. grid = (8, 128)
__global__ __launch_bounds__(256)
void final_kernel(const float* __restrict__ W, const float* __restrict__ bias,
                  float* __restrict__ out)
{
    const float* Ablk = g_concat + (size_t)blockIdx.y * 128 * DM;
    float* Cblk = out + (size_t)blockIdx.y * 128 * DM;
    gemm_block(Ablk, W, bias, Cblk, blockIdx.x);
}

// ---------------------------------------------------------------------------
// Per-token attention: one block per (b, s).
//   qh[d][h] = Yq[h*64 + d]   (projection output is (H, D) flattened)
//   L[d][e]  = (1/8) * sum_h qh[d][h] * kh[e][h]
//   attn     = softmax over e
//   out[d][h]= sum_e attn[d][e] * vh[e][h]
//   concat[b][d*32 + s/64][(s%64)*16 + h] = out[d][h]
// ---------------------------------------------------------------------------
__global__ __launch_bounds__(256)
void attn_kernel()
{
    const int pos = blockIdx.x;          // 0..16383
    const int b   = pos >> 11;           // / 2048
    const int s   = pos & 2047;

    __shared__ float sq[DM];             // (h*64 + d) layout
    __shared__ float sk[DM];             // (h*64 + e) layout
    __shared__ float svT[DM];            // transposed: (e*16 + h)
    __shared__ float sL[HD * HD];        // 64x64 logits / attn

    const int tid = threadIdx.x;
    const float* baseq = g_proj + (size_t)pos * DM;
    const float* basek = g_proj + ((size_t)MTOT + pos) * DM;
    const float* basev = g_proj + ((size_t)2 * MTOT + pos) * DM;

    // Load q, k straight; v transposed (kills stride-64 bank conflicts in PV).
    reinterpret_cast<float4*>(sq)[tid] = reinterpret_cast<const float4*>(baseq)[tid];
    reinterpret_cast<float4*>(sk)[tid] = reinterpret_cast<const float4*>(basek)[tid];
    {
        float4 vv = reinterpret_cast<const float4*>(basev)[tid];
        int n0 = tid * 4;                // elements n0..n0+3; h = n>>6, e = n&63
        int h  = n0 >> 6;
        int e  = n0 & 63;
        svT[(e + 0) * NH + h] = vv.x;
        svT[(e + 1) * NH + h] = vv.y;
        svT[(e + 2) * NH + h] = vv.z;
        svT[(e + 3) * NH + h] = vv.w;
    }
    __syncthreads();

    // Logits: 4096 elements, 16 per thread
#pragma unroll
    for (int i = 0; i < 16; ++i) {
        int idx = tid + i * 256;
        int d = idx >> 6, e = idx & 63;
        float acc = 0.f;
#pragma unroll
        for (int h = 0; h < 16; ++h)
            acc += sq[h * HD + d] * sk[h * HD + e];
        sL[idx] = acc * 0.125f;          // 1/sqrt(64)
    }
    __syncthreads();

    // Softmax over rows (threads 0..63 each own one row of 64)
    if (tid < 64) {
        float* row = sL + tid * 64;
        float m = -1e30f;
#pragma unroll
        for (int e = 0; e < 64; ++e) m = fmaxf(m, row[e]);
        float sum = 0.f;
#pragma unroll
        for (int e = 0; e < 64; ++e) { float t = __expf(row[e] - m); row[e] = t; sum += t; }
        float inv = 1.f / sum;
#pragma unroll
        for (int e = 0; e < 64; ++e) row[e] *= inv;
    }
    __syncthreads();

    // PV + scrambled store: 1024 outputs, 4 per thread
    const int srow = s >> 6;             // s / 64
    const int scol = s & 63;             // s % 64
    float* cbase = g_concat + (size_t)b * SEQ * DM;
#pragma unroll
    for (int i = 0; i < 4; ++i) {
        int o = tid + i * 256;
        int d = o >> 4;                  // 0..63
        int h = o & 15;                  // 0..15
        float acc = 0.f;
#pragma unroll
        for (int e = 0; e < 64; ++e)
            acc += sL[d * 64 + e] * svT[e * NH + h];
        cbase[(size_t)(d * 32 + srow) * DM + scol * NH + h] = acc;
    }
}

// ---------------------------------------------------------------------------
extern "C" void kernel_launch(void* const* d_in, const int* in_sizes, int n_in,
                              void* d_out, int out_size)
{
    const float* q = (const float*)d_in[0];
    const float* k = (const float*)d_in[1];
    const float* v = (const float*)d_in[2];
    const float* W = (const float*)d_in[3];
    const float* b = (const float*)d_in[4];
    float* out = (float*)d_out;

    dim3 gproj(8, 384);   // N blocks x (3 * 128) M blocks
    proj_kernel<<<gproj, 256>>>(q, k, v, W, b);

    attn_kernel<<<MTOT, 256>>>();

    dim3 gfin(8, 128);
    final_kernel<<<gfin, 256>>>(W, b, out);
}

// round 6
// speedup vs baseline: 1.8034x; 1.8034x over previous
#include <cuda_runtime.h>
#include <cuda_bf16.h>
#include <stdint.h>
#include <math.h>

#define DM    1024
#define BATCH 8
#define SEQ   2048
#define NH    16
#define HD    64
#define MTOT  (BATCH * SEQ)     // 16384

// ---------------- scratch: EXACT R1 layout (256MB, proven to load/run) ----------------
__device__ float g_proj[(size_t)3 * MTOT * DM];     // 192MB q/k/v projections (fp32)
__device__ float g_concat[(size_t)MTOT * DM];       // 64MB scrambled concat (fp32)

// ---------------- helpers ----------------
__device__ __forceinline__ void mma16816(float* c, const uint32_t* a, const uint32_t* b) {
    asm volatile("mma.sync.aligned.m16n8k16.row.col.f32.bf16.bf16.f32 "
                 "{%0,%1,%2,%3}, {%4,%5,%6,%7}, {%8,%9}, {%0,%1,%2,%3};"
                 : "+f"(c[0]), "+f"(c[1]), "+f"(c[2]), "+f"(c[3])
                 : "r"(a[0]), "r"(a[1]), "r"(a[2]), "r"(a[3]), "r"(b[0]), "r"(b[1]));
}
__device__ __forceinline__ uint32_t pack_bf2(float a, float b) {
    __nv_bfloat162 t = __floats2bfloat162_rn(a, b);   // .x = a = low 16 bits
    return *reinterpret_cast<uint32_t*>(&t);
}

// ---------------- GEMM geometry: CTA 128x128, BK=32, single-buffered ----------------
// smem planes as uint32 (bf16 pairs). Row pitch 20 u32 (16 data + 4 pad) ->
// fragment LDS banks are disjoint across all 32 lanes (20g mod 32 spread).
#define P32 20
#define NCHUNK 32    // DM / 32

// C[128 x 128@n0] = A[128 x 1024] @ W[n][k]^T + bias. 256 threads, 8 warps (warp 32x64).
// Split numerics: A,W -> hi+lo bf16; acc += Ah*Wh + Ah*Wl + Al*Wh  (fp32 accum).
__device__ __forceinline__ void gemm_body(const float* __restrict__ Arow,
                                          const float* __restrict__ W,
                                          const float* __restrict__ bias,
                                          float* __restrict__ Crow, int n0)
{
    __shared__ uint32_t sAh[128 * P32], sAl[128 * P32];
    __shared__ uint32_t sBh[128 * P32], sBl[128 * P32];

    const int tid  = threadIdx.x;
    const int wid  = tid >> 5;
    const int lane = tid & 31;
    const int wm   = (wid & 3) * 32;      // warp m origin
    const int wn   = (wid >> 2) * 64;     // warp n origin
    const int g    = lane >> 2;           // fragment group id (row within 8)
    const int tq   = lane & 3;            // fragment kpair id

    float acc[2][8][4];
#pragma unroll
    for (int i = 0; i < 2; ++i)
#pragma unroll
        for (int j = 0; j < 8; ++j)
#pragma unroll
            for (int l = 0; l < 4; ++l) acc[i][j][l] = 0.f;

    for (int kc = 0; kc < NCHUNK; ++kc) {
        const int k0 = kc * 32;
        // ---- load 128x32 fp32 of A and W, split to bf16 hi/lo planes ----
#pragma unroll
        for (int j = 0; j < 4; ++j) {
            int idx = tid + j * 256;          // 0..1023
            int r   = idx >> 3;               // 0..127
            int q   = idx & 7;                // float4 index in the 32-wide row
            float4 a = *reinterpret_cast<const float4*>(Arow + (size_t)r * DM + k0 + q * 4);
            float ah0 = __bfloat162float(__float2bfloat16(a.x));
            float ah1 = __bfloat162float(__float2bfloat16(a.y));
            float ah2 = __bfloat162float(__float2bfloat16(a.z));
            float ah3 = __bfloat162float(__float2bfloat16(a.w));
            *reinterpret_cast<uint2*>(&sAh[r * P32 + q * 2]) =
                make_uint2(pack_bf2(ah0, ah1), pack_bf2(ah2, ah3));
            *reinterpret_cast<uint2*>(&sAl[r * P32 + q * 2]) =
                make_uint2(pack_bf2(a.x - ah0, a.y - ah1), pack_bf2(a.z - ah2, a.w - ah3));
            float4 w = *reinterpret_cast<const float4*>(W + (size_t)(n0 + r) * DM + k0 + q * 4);
            float wh0 = __bfloat162float(__float2bfloat16(w.x));
            float wh1 = __bfloat162float(__float2bfloat16(w.y));
            float wh2 = __bfloat162float(__float2bfloat16(w.z));
            float wh3 = __bfloat162float(__float2bfloat16(w.w));
            *reinterpret_cast<uint2*>(&sBh[r * P32 + q * 2]) =
                make_uint2(pack_bf2(wh0, wh1), pack_bf2(wh2, wh3));
            *reinterpret_cast<uint2*>(&sBl[r * P32 + q * 2]) =
                make_uint2(pack_bf2(w.x - wh0, w.y - wh1), pack_bf2(w.z - wh2, w.w - wh3));
        }
        __syncthreads();

        // ---- compute: 2 k16 steps ----
#pragma unroll
        for (int kk = 0; kk < 2; ++kk) {
            const int kb = kk * 8;            // kpair base within the 16-pair chunk
            uint32_t ah[2][4], al[2][4];
#pragma unroll
            for (int mi = 0; mi < 2; ++mi) {
                int r0 = wm + mi * 16 + g;
                int c0 = kb + tq;
                ah[mi][0] = sAh[r0 * P32 + c0];
                ah[mi][1] = sAh[(r0 + 8) * P32 + c0];
                ah[mi][2] = sAh[r0 * P32 + c0 + 4];
                ah[mi][3] = sAh[(r0 + 8) * P32 + c0 + 4];
                al[mi][0] = sAl[r0 * P32 + c0];
                al[mi][1] = sAl[(r0 + 8) * P32 + c0];
                al[mi][2] = sAl[r0 * P32 + c0 + 4];
                al[mi][3] = sAl[(r0 + 8) * P32 + c0 + 4];
            }
#pragma unroll
            for (int np = 0; np < 8; ++np) {
                int rn = wn + np * 8 + g;
                uint32_t bh[2] = { sBh[rn * P32 + kb + tq], sBh[rn * P32 + kb + tq + 4] };
                uint32_t bl[2] = { sBl[rn * P32 + kb + tq], sBl[rn * P32 + kb + tq + 4] };
#pragma unroll
                for (int mi = 0; mi < 2; ++mi) {
                    mma16816(acc[mi][np], ah[mi], bh);
                    mma16816(acc[mi][np], ah[mi], bl);
                    mma16816(acc[mi][np], al[mi], bh);
                }
            }
        }
        __syncthreads();
    }

    // ---- epilogue: C frag rows g/g+8, cols (lane&3)*2 ----
    const int en = tq * 2;
#pragma unroll
    for (int mi = 0; mi < 2; ++mi) {
#pragma unroll
        for (int np = 0; np < 8; ++np) {
            int col = n0 + wn + np * 8 + en;
            float bx = __ldg(bias + col), by = __ldg(bias + col + 1);
            size_t r0 = (size_t)(wm + mi * 16 + g);
            float2 v0 = { acc[mi][np][0] + bx, acc[mi][np][1] + by };
            float2 v1 = { acc[mi][np][2] + bx, acc[mi][np][3] + by };
            *reinterpret_cast<float2*>(Crow + r0 * DM + col)       = v0;
            *reinterpret_cast<float2*>(Crow + (r0 + 8) * DM + col) = v1;
        }
    }
}

// Projection GEMM: q,k,v stacked. grid = (8, 384)
__global__ __launch_bounds__(256)
void proj_kernel(const float* __restrict__ q, const float* __restrict__ k,
                 const float* __restrict__ v, const float* __restrict__ W,
                 const float* __restrict__ bias)
{
    const int bm  = blockIdx.y;        // 0..383
    const int sel = bm >> 7;           // 0:q 1:k 2:v
    const float* A = (sel == 0) ? q : ((sel == 1) ? k : v);
    const int rowblk = bm & 127;
    gemm_body(A + (size_t)rowblk * 128 * DM, W, bias,
              g_proj + ((size_t)sel * MTOT + (size_t)rowblk * 128) * DM,
              blockIdx.x * 128);
}

// Final GEMM: out = concat @ W^T + bias. grid = (8, 128)
__global__ __launch_bounds__(256)
void final_kernel(const float* __restrict__ W, const float* __restrict__ bias,
                  float* __restrict__ out)
{
    gemm_body(g_concat + (size_t)blockIdx.y * 128 * DM, W, bias,
              out + (size_t)blockIdx.y * 128 * DM, blockIdx.x * 128);
}

// ---------------- per-token attention: EXACT R1 version (proven) ----------------
__global__ __launch_bounds__(256)
void attn_kernel()
{
    const int pos = blockIdx.x;          // 0..16383
    const int b   = pos >> 11;
    const int s   = pos & 2047;

    __shared__ float sq[DM];
    __shared__ float sk[DM];
    __shared__ float svT[DM];            // transposed: (e*16 + h)
    __shared__ float sL[HD * HD];

    const int tid = threadIdx.x;
    const float* baseq = g_proj + (size_t)pos * DM;
    const float* basek = g_proj + ((size_t)MTOT + pos) * DM;
    const float* basev = g_proj + ((size_t)2 * MTOT + pos) * DM;

    reinterpret_cast<float4*>(sq)[tid] = reinterpret_cast<const float4*>(baseq)[tid];
    reinterpret_cast<float4*>(sk)[tid] = reinterpret_cast<const float4*>(basek)[tid];
    {
        float4 vv = reinterpret_cast<const float4*>(basev)[tid];
        int n0 = tid * 4;
        int h  = n0 >> 6;
        int e  = n0 & 63;
        svT[(e + 0) * NH + h] = vv.x;
        svT[(e + 1) * NH + h] = vv.y;
        svT[(e + 2) * NH + h] = vv.z;
        svT[(e + 3) * NH + h] = vv.w;
    }
    __syncthreads();

#pragma unroll
    for (int i = 0; i < 16; ++i) {
        int idx = tid + i * 256;
        int d = idx >> 6, e = idx & 63;
        float acc = 0.f;
#pragma unroll
        for (int h = 0; h < 16; ++h)
            acc += sq[h * HD + d] * sk[h * HD + e];
        sL[idx] = acc * 0.125f;
    }
    __syncthreads();

    if (tid < 64) {
        float* row = sL + tid * 64;
        float m = -1e30f;
#pragma unroll
        for (int e = 0; e < 64; ++e) m = fmaxf(m, row[e]);
        float sum = 0.f;
#pragma unroll
        for (int e = 0; e < 64; ++e) { float t = __expf(row[e] - m); row[e] = t; sum += t; }
        float inv = 1.f / sum;
#pragma unroll
        for (int e = 0; e < 64; ++e) row[e] *= inv;
    }
    __syncthreads();

    const int srow = s >> 6;
    const int scol = s & 63;
    float* cbase = g_concat + (size_t)b * SEQ * DM;
#pragma unroll
    for (int i = 0; i < 4; ++i) {
        int o = tid + i * 256;
        int d = o >> 4;
        int h = o & 15;
        float acc = 0.f;
#pragma unroll
        for (int e = 0; e < 64; ++e)
            acc += sL[d * 64 + e] * svT[e * NH + h];
        cbase[(size_t)(d * 32 + srow) * DM + scol * NH + h] = acc;
    }
}

// ---------------------------------------------------------------------------
extern "C" void kernel_launch(void* const* d_in, const int* in_sizes, int n_in,
                              void* d_out, int out_size)
{
    const float* q = (const float*)d_in[0];
    const float* k = (const float*)d_in[1];
    const float* v = (const float*)d_in[2];
    const float* W = (const float*)d_in[3];
    const float* b = (const float*)d_in[4];
    float* out = (float*)d_out;

    proj_kernel<<<dim3(8, 384), 256>>>(q, k, v, W, b);

    attn_kernel<<<MTOT, 256>>>();

    final_kernel<<<dim3(8, 128), 256>>>(W, b, out);
}

// round 7
// speedup vs baseline: 2.2015x; 1.2208x over previous
#include <cuda_runtime.h>
#include <cuda_bf16.h>
#include <stdint.h>
#include <math.h>

#define DM    1024
#define BATCH 8
#define SEQ   2048
#define NH    16
#define HD    64
#define MTOT  (BATCH * SEQ)     // 16384

// ---------------- scratch ----------------
__device__ float         g_proj[(size_t)3 * MTOT * DM];   // 192MB q/k/v projections (fp32)
__device__ float         g_concat[(size_t)MTOT * DM];     // 64MB scrambled concat (fp32)
__device__ __nv_bfloat16 g_W_hi[(size_t)DM * DM];         // 2MB
__device__ __nv_bfloat16 g_W_lo[(size_t)DM * DM];         // 2MB

// ---------------- helpers ----------------
__device__ __forceinline__ void mma16816(float* c, const uint32_t* a, const uint32_t* b) {
    asm volatile("mma.sync.aligned.m16n8k16.row.col.f32.bf16.bf16.f32 "
                 "{%0,%1,%2,%3}, {%4,%5,%6,%7}, {%8,%9}, {%0,%1,%2,%3};"
                 : "+f"(c[0]), "+f"(c[1]), "+f"(c[2]), "+f"(c[3])
                 : "r"(a[0]), "r"(a[1]), "r"(a[2]), "r"(a[3]), "r"(b[0]), "r"(b[1]));
}
__device__ __forceinline__ uint32_t pack_bf2(float a, float b) {
    __nv_bfloat162 t = __floats2bfloat162_rn(a, b);   // .x = a = low 16 bits
    return *reinterpret_cast<uint32_t*>(&t);
}

// ---------------- W pre-split: fp32 -> bf16 hi/lo planes ----------------
__global__ __launch_bounds__(256)
void convert_w(const float* __restrict__ W)
{
    int i = blockIdx.x * blockDim.x + threadIdx.x;     // float4 index, 262144 total
    float4 x = reinterpret_cast<const float4*>(W)[i];
    float h0 = __bfloat162float(__float2bfloat16(x.x));
    float h1 = __bfloat162float(__float2bfloat16(x.y));
    float h2 = __bfloat162float(__float2bfloat16(x.z));
    float h3 = __bfloat162float(__float2bfloat16(x.w));
    reinterpret_cast<uint2*>(g_W_hi)[i] = make_uint2(pack_bf2(h0, h1), pack_bf2(h2, h3));
    reinterpret_cast<uint2*>(g_W_lo)[i] =
        make_uint2(pack_bf2(x.x - h0, x.y - h1), pack_bf2(x.z - h2, x.w - h3));
}

// ---------------- GEMM: CTA 128x128, BK=32, register-prefetch pipeline ----------------
#define P32 20        // smem row pitch in u32 (16 data + 4 pad)
#define NCHUNK 32     // DM / 32

// C[128 x 128@n0] = A[128 x 1024] @ W^T + bias; split numerics Ah*Wh + Ah*Wl + Al*Wh.
__device__ __forceinline__ void gemm_body(const float* __restrict__ Arow,
                                          const float* __restrict__ bias,
                                          float* __restrict__ Crow, int n0)
{
    __shared__ uint32_t sAh[128 * P32], sAl[128 * P32];
    __shared__ uint32_t sBh[128 * P32], sBl[128 * P32];

    const int tid  = threadIdx.x;
    const int wid  = tid >> 5;
    const int lane = tid & 31;
    const int wm   = (wid & 3) * 32;
    const int wn   = (wid >> 2) * 64;
    const int g    = lane >> 2;
    const int tq   = lane & 3;

    float acc[2][8][4];
#pragma unroll
    for (int i = 0; i < 2; ++i)
#pragma unroll
        for (int j = 0; j < 8; ++j)
#pragma unroll
            for (int l = 0; l < 4; ++l) acc[i][j][l] = 0.f;

    float4 pa[4];
    uint2  pwh[4], pwl[4];

#define PREF(kc) do { \
    const int k0_ = (kc) * 32; \
    _Pragma("unroll") \
    for (int j = 0; j < 4; ++j) { \
        int idx = tid + j * 256, r = idx >> 3, q = idx & 7; \
        pa[j]  = *reinterpret_cast<const float4*>(Arow + (size_t)r * DM + k0_ + q * 4); \
        pwh[j] = *reinterpret_cast<const uint2*>( \
            (const char*)g_W_hi + ((size_t)(n0 + r) * DM + k0_ + q * 4) * 2); \
        pwl[j] = *reinterpret_cast<const uint2*>( \
            (const char*)g_W_lo + ((size_t)(n0 + r) * DM + k0_ + q * 4) * 2); \
    } } while (0)

#define STORE() do { \
    _Pragma("unroll") \
    for (int j = 0; j < 4; ++j) { \
        int idx = tid + j * 256, r = idx >> 3, q = idx & 7; \
        float4 a = pa[j]; \
        float h0 = __bfloat162float(__float2bfloat16(a.x)); \
        float h1 = __bfloat162float(__float2bfloat16(a.y)); \
        float h2 = __bfloat162float(__float2bfloat16(a.z)); \
        float h3 = __bfloat162float(__float2bfloat16(a.w)); \
        *reinterpret_cast<uint2*>(&sAh[r * P32 + q * 2]) = \
            make_uint2(pack_bf2(h0, h1), pack_bf2(h2, h3)); \
        *reinterpret_cast<uint2*>(&sAl[r * P32 + q * 2]) = \
            make_uint2(pack_bf2(a.x - h0, a.y - h1), pack_bf2(a.z - h2, a.w - h3)); \
        *reinterpret_cast<uint2*>(&sBh[r * P32 + q * 2]) = pwh[j]; \
        *reinterpret_cast<uint2*>(&sBl[r * P32 + q * 2]) = pwl[j]; \
    } } while (0)

    PREF(0);

    for (int kc = 0; kc < NCHUNK; ++kc) {
        STORE();
        __syncthreads();
        if (kc + 1 < NCHUNK) PREF(kc + 1);   // LDG latency hidden behind MMAs below

#pragma unroll
        for (int kk = 0; kk < 2; ++kk) {
            const int kb = kk * 8;
            uint32_t ah[2][4], al[2][4];
#pragma unroll
            for (int mi = 0; mi < 2; ++mi) {
                int r0 = wm + mi * 16 + g;
                int c0 = kb + tq;
                ah[mi][0] = sAh[r0 * P32 + c0];
                ah[mi][1] = sAh[(r0 + 8) * P32 + c0];
                ah[mi][2] = sAh[r0 * P32 + c0 + 4];
                ah[mi][3] = sAh[(r0 + 8) * P32 + c0 + 4];
                al[mi][0] = sAl[r0 * P32 + c0];
                al[mi][1] = sAl[(r0 + 8) * P32 + c0];
                al[mi][2] = sAl[r0 * P32 + c0 + 4];
                al[mi][3] = sAl[(r0 + 8) * P32 + c0 + 4];
            }
#pragma unroll
            for (int np = 0; np < 8; ++np) {
                int rn = wn + np * 8 + g;
                uint32_t bh[2] = { sBh[rn * P32 + kb + tq], sBh[rn * P32 + kb + tq + 4] };
                uint32_t bl[2] = { sBl[rn * P32 + kb + tq], sBl[rn * P32 + kb + tq + 4] };
#pragma unroll
                for (int mi = 0; mi < 2; ++mi) {
                    mma16816(acc[mi][np], ah[mi], bh);
                    mma16816(acc[mi][np], ah[mi], bl);
                    mma16816(acc[mi][np], al[mi], bh);
                }
            }
        }
        __syncthreads();
    }
#undef PREF
#undef STORE

    const int en = tq * 2;
#pragma unroll
    for (int mi = 0; mi < 2; ++mi) {
#pragma unroll
        for (int np = 0; np < 8; ++np) {
            int col = n0 + wn + np * 8 + en;
            float bx = __ldg(bias + col), by = __ldg(bias + col + 1);
            size_t r0 = (size_t)(wm + mi * 16 + g);
            float2 v0 = { acc[mi][np][0] + bx, acc[mi][np][1] + by };
            float2 v1 = { acc[mi][np][2] + bx, acc[mi][np][3] + by };
            *reinterpret_cast<float2*>(Crow + r0 * DM + col)       = v0;
            *reinterpret_cast<float2*>(Crow + (r0 + 8) * DM + col) = v1;
        }
    }
}

__global__ __launch_bounds__(256)
void proj_kernel(const float* __restrict__ q, const float* __restrict__ k,
                 const float* __restrict__ v, const float* __restrict__ bias)
{
    const int bm  = blockIdx.y;        // 0..383
    const int sel = bm >> 7;
    const float* A = (sel == 0) ? q : ((sel == 1) ? k : v);
    const int rowblk = bm & 127;
    gemm_body(A + (size_t)rowblk * 128 * DM, bias,
              g_proj + ((size_t)sel * MTOT + (size_t)rowblk * 128) * DM,
              blockIdx.x * 128);
}

__global__ __launch_bounds__(256)
void final_kernel(const float* __restrict__ bias, float* __restrict__ out)
{
    gemm_body(g_concat + (size_t)blockIdx.y * 128 * DM, bias,
              out + (size_t)blockIdx.y * 128 * DM, blockIdx.x * 128);
}

// ---------------- per-token attention, register-tiled ----------------
#define SLP 68    // sL row pitch (floats): 16B-aligned, PV reads conflict-free

__global__ __launch_bounds__(256)
void attn_kernel()
{
    const int pos = blockIdx.x;          // 0..16383
    const int b   = pos >> 11;
    const int s   = pos & 2047;

    __shared__ float sq[DM];
    __shared__ float sk[DM];
    __shared__ float svT[DM];            // transposed: (e*16 + h)
    __shared__ float sL[HD * SLP];

    const int tid = threadIdx.x;
    const float* baseq = g_proj + (size_t)pos * DM;
    const float* basek = g_proj + ((size_t)MTOT + pos) * DM;
    const float* basev = g_proj + ((size_t)2 * MTOT + pos) * DM;

    reinterpret_cast<float4*>(sq)[tid] = reinterpret_cast<const float4*>(baseq)[tid];
    reinterpret_cast<float4*>(sk)[tid] = reinterpret_cast<const float4*>(basek)[tid];
    {
        float4 vv = reinterpret_cast<const float4*>(basev)[tid];
        int n0 = tid * 4;
        int h  = n0 >> 6;
        int e  = n0 & 63;
        svT[(e + 0) * NH + h] = vv.x;
        svT[(e + 1) * NH + h] = vv.y;
        svT[(e + 2) * NH + h] = vv.z;
        svT[(e + 3) * NH + h] = vv.w;
    }
    __syncthreads();

    // ---- logits: 4x4 register tile per thread (16x16 thread grid) ----
    {
        const int ty = tid >> 4;          // d-tile: rows ty*4..+3
        const int tx = tid & 15;          // e-tile: cols tx*4..+3
        float c[4][4];
#pragma unroll
        for (int i = 0; i < 4; ++i)
#pragma unroll
            for (int j = 0; j < 4; ++j) c[i][j] = 0.f;
#pragma unroll
        for (int h = 0; h < 16; ++h) {
            float4 qa = *reinterpret_cast<const float4*>(&sq[h * HD + ty * 4]);
            float4 kb = *reinterpret_cast<const float4*>(&sk[h * HD + tx * 4]);
            const float qv[4] = { qa.x, qa.y, qa.z, qa.w };
            const float kv[4] = { kb.x, kb.y, kb.z, kb.w };
#pragma unroll
            for (int i = 0; i < 4; ++i)
#pragma unroll
                for (int j = 0; j < 4; ++j)
                    c[i][j] += qv[i] * kv[j];
        }
#pragma unroll
        for (int i = 0; i < 4; ++i) {
            float4 v = { c[i][0] * 0.125f, c[i][1] * 0.125f,
                         c[i][2] * 0.125f, c[i][3] * 0.125f };
            *reinterpret_cast<float4*>(&sL[(ty * 4 + i) * SLP + tx * 4]) = v;
        }
    }
    __syncthreads();

    // ---- softmax: 4 lanes per row, 16 elems each, shfl reduce ----
    {
        const int row = tid >> 2;
        const int sub = tid & 3;
        float* rp = sL + row * SLP + sub * 16;
        float4 v0 = *reinterpret_cast<float4*>(rp + 0);
        float4 v1 = *reinterpret_cast<float4*>(rp + 4);
        float4 v2 = *reinterpret_cast<float4*>(rp + 8);
        float4 v3 = *reinterpret_cast<float4*>(rp + 12);
        float m = fmaxf(fmaxf(fmaxf(v0.x, v0.y), fmaxf(v0.z, v0.w)),
                        fmaxf(fmaxf(v1.x, v1.y), fmaxf(v1.z, v1.w)));
        m = fmaxf(m, fmaxf(fmaxf(fmaxf(v2.x, v2.y), fmaxf(v2.z, v2.w)),
                           fmaxf(fmaxf(v3.x, v3.y), fmaxf(v3.z, v3.w))));
        m = fmaxf(m, __shfl_xor_sync(0xFFFFFFFFu, m, 1));
        m = fmaxf(m, __shfl_xor_sync(0xFFFFFFFFu, m, 2));
        v0.x = __expf(v0.x - m); v0.y = __expf(v0.y - m);
        v0.z = __expf(v0.z - m); v0.w = __expf(v0.w - m);
        v1.x = __expf(v1.x - m); v1.y = __expf(v1.y - m);
        v1.z = __expf(v1.z - m); v1.w = __expf(v1.w - m);
        v2.x = __expf(v2.x - m); v2.y = __expf(v2.y - m);
        v2.z = __expf(v2.z - m); v2.w = __expf(v2.w - m);
        v3.x = __expf(v3.x - m); v3.y = __expf(v3.y - m);
        v3.z = __expf(v3.z - m); v3.w = __expf(v3.w - m);
        float sum = (v0.x + v0.y + v0.z + v0.w) + (v1.x + v1.y + v1.z + v1.w)
                  + (v2.x + v2.y + v2.z + v2.w) + (v3.x + v3.y + v3.z + v3.w);
        sum += __shfl_xor_sync(0xFFFFFFFFu, sum, 1);
        sum += __shfl_xor_sync(0xFFFFFFFFu, sum, 2);
        float inv = 1.f / sum;
        v0.x *= inv; v0.y *= inv; v0.z *= inv; v0.w *= inv;
        v1.x *= inv; v1.y *= inv; v1.z *= inv; v1.w *= inv;
        v2.x *= inv; v2.y *= inv; v2.z *= inv; v2.w *= inv;
        v3.x *= inv; v3.y *= inv; v3.z *= inv; v3.w *= inv;
        *reinterpret_cast<float4*>(rp + 0)  = v0;
        *reinterpret_cast<float4*>(rp + 4)  = v1;
        *reinterpret_cast<float4*>(rp + 8)  = v2;
        *reinterpret_cast<float4*>(rp + 12) = v3;
    }
    __syncthreads();

    // ---- PV: thread = (d, h-quad); float4 accumulate over e ----
    {
        const int d  = tid >> 2;
        const int hq = tid & 3;
        float4 acc = { 0.f, 0.f, 0.f, 0.f };
        const float* lrow = sL + d * SLP;
#pragma unroll 8
        for (int e = 0; e < 64; ++e) {
            float p = lrow[e];
            float4 vv = *reinterpret_cast<const float4*>(&svT[e * NH + hq * 4]);
            acc.x += p * vv.x; acc.y += p * vv.y;
            acc.z += p * vv.z; acc.w += p * vv.w;
        }
        const int srow = s >> 6;
        const int scol = s & 63;
        float* dst = g_concat + (size_t)b * SEQ * DM
                   + (size_t)(d * 32 + srow) * DM + scol * NH + hq * 4;
        *reinterpret_cast<float4*>(dst) = acc;
    }
}

// ---------------------------------------------------------------------------
extern "C" void kernel_launch(void* const* d_in, const int* in_sizes, int n_in,
                              void* d_out, int out_size)
{
    const float* q = (const float*)d_in[0];
    const float* k = (const float*)d_in[1];
    const float* v = (const float*)d_in[2];
    const float* W = (const float*)d_in[3];
    const float* b = (const float*)d_in[4];
    float* out = (float*)d_out;

    convert_w<<<DM * DM / 4 / 256, 256>>>(W);

    proj_kernel<<<dim3(8, 384), 256>>>(q, k, v, b);

    attn_kernel<<<MTOT, 256>>>();

    final_kernel<<<dim3(8, 128), 256>>>(b, out);
}

// round 8
// speedup vs baseline: 2.3537x; 1.0691x over previous
#include <cuda_runtime.h>
#include <cuda_bf16.h>
#include <stdint.h>
#include <math.h>

#define DM    1024
#define BATCH 8
#define SEQ   2048
#define NH    16
#define HD    64
#define MTOT  (BATCH * SEQ)     // 16384

// ---------------- scratch ----------------
__device__ float         g_proj[(size_t)3 * MTOT * DM];   // 192MB q/k/v projections (fp32)
__device__ float         g_concat[(size_t)MTOT * DM];     // 64MB scrambled concat (fp32)
__device__ __nv_bfloat16 g_W_hi[(size_t)DM * DM];         // 2MB
__device__ __nv_bfloat16 g_W_lo[(size_t)DM * DM];         // 2MB

// ---------------- helpers ----------------
__device__ __forceinline__ void mma16816(float* c, const uint32_t* a, const uint32_t* b) {
    asm volatile("mma.sync.aligned.m16n8k16.row.col.f32.bf16.bf16.f32 "
                 "{%0,%1,%2,%3}, {%4,%5,%6,%7}, {%8,%9}, {%0,%1,%2,%3};"
                 : "+f"(c[0]), "+f"(c[1]), "+f"(c[2]), "+f"(c[3])
                 : "r"(a[0]), "r"(a[1]), "r"(a[2]), "r"(a[3]), "r"(b[0]), "r"(b[1]));
}
__device__ __forceinline__ uint32_t pack_bf2(float a, float b) {
    __nv_bfloat162 t = __floats2bfloat162_rn(a, b);   // .x = a = low 16 bits
    return *reinterpret_cast<uint32_t*>(&t);
}

// ---------------- W pre-split: fp32 -> bf16 hi/lo planes ----------------
__global__ __launch_bounds__(256)
void convert_w(const float* __restrict__ W)
{
    int i = blockIdx.x * blockDim.x + threadIdx.x;     // float4 index, 262144 total
    float4 x = reinterpret_cast<const float4*>(W)[i];
    float h0 = __bfloat162float(__float2bfloat16(x.x));
    float h1 = __bfloat162float(__float2bfloat16(x.y));
    float h2 = __bfloat162float(__float2bfloat16(x.z));
    float h3 = __bfloat162float(__float2bfloat16(x.w));
    reinterpret_cast<uint2*>(g_W_hi)[i] = make_uint2(pack_bf2(h0, h1), pack_bf2(h2, h3));
    reinterpret_cast<uint2*>(g_W_lo)[i] =
        make_uint2(pack_bf2(x.x - h0, x.y - h1), pack_bf2(x.z - h2, x.w - h3));
}

// ---------------- GEMM: CTA 128x128, 512 threads, warp tile 32x32, BK=32 ----------------
#define P32 20        // smem row pitch in u32 (16 data + 4 pad)
#define NCHUNK 32     // DM / 32

// C[128 x 128@n0] = A[128 x 1024] @ W^T + bias; split numerics Ah*Wh + Ah*Wl + Al*Wh.
__device__ __forceinline__ void gemm_body(const float* __restrict__ Arow,
                                          const float* __restrict__ bias,
                                          float* __restrict__ Crow, int n0)
{
    __shared__ uint32_t sAh[128 * P32], sAl[128 * P32];
    __shared__ uint32_t sBh[128 * P32], sBl[128 * P32];

    const int tid  = threadIdx.x;
    const int wid  = tid >> 5;            // 0..15
    const int lane = tid & 31;
    const int wm   = (wid & 3) * 32;      // 4 m-groups
    const int wn   = (wid >> 2) * 32;     // 4 n-groups
    const int g    = lane >> 2;
    const int tq   = lane & 3;

    float acc[2][4][4];
#pragma unroll
    for (int i = 0; i < 2; ++i)
#pragma unroll
        for (int j = 0; j < 4; ++j)
#pragma unroll
            for (int l = 0; l < 4; ++l) acc[i][j][l] = 0.f;

    float4 pa[2];
    uint2  pwh[2], pwl[2];

#define PREF(kc) do { \
    const int k0_ = (kc) * 32; \
    _Pragma("unroll") \
    for (int j = 0; j < 2; ++j) { \
        int idx = tid + j * 512, r = idx >> 3, q = idx & 7; \
        pa[j]  = *reinterpret_cast<const float4*>(Arow + (size_t)r * DM + k0_ + q * 4); \
        pwh[j] = *reinterpret_cast<const uint2*>( \
            (const char*)g_W_hi + ((size_t)(n0 + r) * DM + k0_ + q * 4) * 2); \
        pwl[j] = *reinterpret_cast<const uint2*>( \
            (const char*)g_W_lo + ((size_t)(n0 + r) * DM + k0_ + q * 4) * 2); \
    } } while (0)

#define STORE() do { \
    _Pragma("unroll") \
    for (int j = 0; j < 2; ++j) { \
        int idx = tid + j * 512, r = idx >> 3, q = idx & 7; \
        float4 a = pa[j]; \
        float h0 = __bfloat162float(__float2bfloat16(a.x)); \
        float h1 = __bfloat162float(__float2bfloat16(a.y)); \
        float h2 = __bfloat162float(__float2bfloat16(a.z)); \
        float h3 = __bfloat162float(__float2bfloat16(a.w)); \
        *reinterpret_cast<uint2*>(&sAh[r * P32 + q * 2]) = \
            make_uint2(pack_bf2(h0, h1), pack_bf2(h2, h3)); \
        *reinterpret_cast<uint2*>(&sAl[r * P32 + q * 2]) = \
            make_uint2(pack_bf2(a.x - h0, a.y - h1), pack_bf2(a.z - h2, a.w - h3)); \
        *reinterpret_cast<uint2*>(&sBh[r * P32 + q * 2]) = pwh[j]; \
        *reinterpret_cast<uint2*>(&sBl[r * P32 + q * 2]) = pwl[j]; \
    } } while (0)

    PREF(0);

    for (int kc = 0; kc < NCHUNK; ++kc) {
        STORE();
        __syncthreads();
        if (kc + 1 < NCHUNK) PREF(kc + 1);   // LDG latency hidden behind MMAs below

#pragma unroll
        for (int kk = 0; kk < 2; ++kk) {
            const int kb = kk * 8;
            uint32_t ah[2][4], al[2][4];
#pragma unroll
            for (int mi = 0; mi < 2; ++mi) {
                int r0 = wm + mi * 16 + g;
                int c0 = kb + tq;
                ah[mi][0] = sAh[r0 * P32 + c0];
                ah[mi][1] = sAh[(r0 + 8) * P32 + c0];
                ah[mi][2] = sAh[r0 * P32 + c0 + 4];
                ah[mi][3] = sAh[(r0 + 8) * P32 + c0 + 4];
                al[mi][0] = sAl[r0 * P32 + c0];
                al[mi][1] = sAl[(r0 + 8) * P32 + c0];
                al[mi][2] = sAl[r0 * P32 + c0 + 4];
                al[mi][3] = sAl[(r0 + 8) * P32 + c0 + 4];
            }
#pragma unroll
            for (int np = 0; np < 4; ++np) {
                int rn = wn + np * 8 + g;
                uint32_t bh[2] = { sBh[rn * P32 + kb + tq], sBh[rn * P32 + kb + tq + 4] };
                uint32_t bl[2] = { sBl[rn * P32 + kb + tq], sBl[rn * P32 + kb + tq + 4] };
#pragma unroll
                for (int mi = 0; mi < 2; ++mi) {
                    mma16816(acc[mi][np], ah[mi], bh);
                    mma16816(acc[mi][np], ah[mi], bl);
                    mma16816(acc[mi][np], al[mi], bh);
                }
            }
        }
        __syncthreads();
    }
#undef PREF
#undef STORE

    const int en = tq * 2;
#pragma unroll
    for (int mi = 0; mi < 2; ++mi) {
#pragma unroll
        for (int np = 0; np < 4; ++np) {
            int col = n0 + wn + np * 8 + en;
            float bx = __ldg(bias + col), by = __ldg(bias + col + 1);
            size_t r0 = (size_t)(wm + mi * 16 + g);
            float2 v0 = { acc[mi][np][0] + bx, acc[mi][np][1] + by };
            float2 v1 = { acc[mi][np][2] + bx, acc[mi][np][3] + by };
            *reinterpret_cast<float2*>(Crow + r0 * DM + col)       = v0;
            *reinterpret_cast<float2*>(Crow + (r0 + 8) * DM + col) = v1;
        }
    }
}

__global__ __launch_bounds__(512)
void proj_kernel(const float* __restrict__ q, const float* __restrict__ k,
                 const float* __restrict__ v, const float* __restrict__ bias)
{
    const int bm  = blockIdx.y;        // 0..383
    const int sel = bm >> 7;
    const float* A = (sel == 0) ? q : ((sel == 1) ? k : v);
    const int rowblk = bm & 127;
    gemm_body(A + (size_t)rowblk * 128 * DM, bias,
              g_proj + ((size_t)sel * MTOT + (size_t)rowblk * 128) * DM,
              blockIdx.x * 128);
}

__global__ __launch_bounds__(512)
void final_kernel(const float* __restrict__ bias, float* __restrict__ out)
{
    gemm_body(g_concat + (size_t)blockIdx.y * 128 * DM, bias,
              out + (size_t)blockIdx.y * 128 * DM, blockIdx.x * 128);
}

// ---------------- per-token attention, register-tiled ----------------
#define SLP 68    // sL row pitch (floats)

__global__ __launch_bounds__(256)
void attn_kernel()
{
    const int pos = blockIdx.x;          // 0..16383
    const int b   = pos >> 11;
    const int s   = pos & 2047;

    __shared__ float sq[DM];
    __shared__ float sk[DM];
    __shared__ float svT[DM];            // transposed: (e*16 + h)
    __shared__ float sL[HD * SLP];

    const int tid = threadIdx.x;
    const float* baseq = g_proj + (size_t)pos * DM;
    const float* basek = g_proj + ((size_t)MTOT + pos) * DM;
    const float* basev = g_proj + ((size_t)2 * MTOT + pos) * DM;

    reinterpret_cast<float4*>(sq)[tid] = reinterpret_cast<const float4*>(baseq)[tid];
    reinterpret_cast<float4*>(sk)[tid] = reinterpret_cast<const float4*>(basek)[tid];
    {
        float4 vv = reinterpret_cast<const float4*>(basev)[tid];
        int n0 = tid * 4;
        int h  = n0 >> 6;
        int e  = n0 & 63;
        svT[(e + 0) * NH + h] = vv.x;
        svT[(e + 1) * NH + h] = vv.y;
        svT[(e + 2) * NH + h] = vv.z;
        svT[(e + 3) * NH + h] = vv.w;
    }
    __syncthreads();

    // ---- logits: 4x4 register tile per thread ----
    {
        const int ty = tid >> 4;
        const int tx = tid & 15;
        float c[4][4];
#pragma unroll
        for (int i = 0; i < 4; ++i)
#pragma unroll
            for (int j = 0; j < 4; ++j) c[i][j] = 0.f;
#pragma unroll
        for (int h = 0; h < 16; ++h) {
            float4 qa = *reinterpret_cast<const float4*>(&sq[h * HD + ty * 4]);
            float4 kb = *reinterpret_cast<const float4*>(&sk[h * HD + tx * 4]);
            const float qv[4] = { qa.x, qa.y, qa.z, qa.w };
            const float kv[4] = { kb.x, kb.y, kb.z, kb.w };
#pragma unroll
            for (int i = 0; i < 4; ++i)
#pragma unroll
                for (int j = 0; j < 4; ++j)
                    c[i][j] += qv[i] * kv[j];
        }
#pragma unroll
        for (int i = 0; i < 4; ++i) {
            float4 v = { c[i][0] * 0.125f, c[i][1] * 0.125f,
                         c[i][2] * 0.125f, c[i][3] * 0.125f };
            *reinterpret_cast<float4*>(&sL[(ty * 4 + i) * SLP + tx * 4]) = v;
        }
    }
    __syncthreads();

    // ---- softmax: 4 lanes per row, shfl reduce ----
    {
        const int row = tid >> 2;
        const int sub = tid & 3;
        float* rp = sL + row * SLP + sub * 16;
        float4 v0 = *reinterpret_cast<float4*>(rp + 0);
        float4 v1 = *reinterpret_cast<float4*>(rp + 4);
        float4 v2 = *reinterpret_cast<float4*>(rp + 8);
        float4 v3 = *reinterpret_cast<float4*>(rp + 12);
        float m = fmaxf(fmaxf(fmaxf(v0.x, v0.y), fmaxf(v0.z, v0.w)),
                        fmaxf(fmaxf(v1.x, v1.y), fmaxf(v1.z, v1.w)));
        m = fmaxf(m, fmaxf(fmaxf(fmaxf(v2.x, v2.y), fmaxf(v2.z, v2.w)),
                           fmaxf(fmaxf(v3.x, v3.y), fmaxf(v3.z, v3.w))));
        m = fmaxf(m, __shfl_xor_sync(0xFFFFFFFFu, m, 1));
        m = fmaxf(m, __shfl_xor_sync(0xFFFFFFFFu, m, 2));
        v0.x = __expf(v0.x - m); v0.y = __expf(v0.y - m);
        v0.z = __expf(v0.z - m); v0.w = __expf(v0.w - m);
        v1.x = __expf(v1.x - m); v1.y = __expf(v1.y - m);
        v1.z = __expf(v1.z - m); v1.w = __expf(v1.w - m);
        v2.x = __expf(v2.x - m); v2.y = __expf(v2.y - m);
        v2.z = __expf(v2.z - m); v2.w = __expf(v2.w - m);
        v3.x = __expf(v3.x - m); v3.y = __expf(v3.y - m);
        v3.z = __expf(v3.z - m); v3.w = __expf(v3.w - m);
        float sum = (v0.x + v0.y + v0.z + v0.w) + (v1.x + v1.y + v1.z + v1.w)
                  + (v2.x + v2.y + v2.z + v2.w) + (v3.x + v3.y + v3.z + v3.w);
        sum += __shfl_xor_sync(0xFFFFFFFFu, sum, 1);
        sum += __shfl_xor_sync(0xFFFFFFFFu, sum, 2);
        float inv = 1.f / sum;
        v0.x *= inv; v0.y *= inv; v0.z *= inv; v0.w *= inv;
        v1.x *= inv; v1.y *= inv; v1.z *= inv; v1.w *= inv;
        v2.x *= inv; v2.y *= inv; v2.z *= inv; v2.w *= inv;
        v3.x *= inv; v3.y *= inv; v3.z *= inv; v3.w *= inv;
        *reinterpret_cast<float4*>(rp + 0)  = v0;
        *reinterpret_cast<float4*>(rp + 4)  = v1;
        *reinterpret_cast<float4*>(rp + 8)  = v2;
        *reinterpret_cast<float4*>(rp + 12) = v3;
    }
    __syncthreads();

    // ---- PV ----
    {
        const int d  = tid >> 2;
        const int hq = tid & 3;
        float4 acc = { 0.f, 0.f, 0.f, 0.f };
        const float* lrow = sL + d * SLP;
#pragma unroll 8
        for (int e = 0; e < 64; ++e) {
            float p = lrow[e];
            float4 vv = *reinterpret_cast<const float4*>(&svT[e * NH + hq * 4]);
            acc.x += p * vv.x; acc.y += p * vv.y;
            acc.z += p * vv.z; acc.w += p * vv.w;
        }
        const int srow = s >> 6;
        const int scol = s & 63;
        float* dst = g_concat + (size_t)b * SEQ * DM
                   + (size_t)(d * 32 + srow) * DM + scol * NH + hq * 4;
        *reinterpret_cast<float4*>(dst) = acc;
    }
}

// ---------------------------------------------------------------------------
extern "C" void kernel_launch(void* const* d_in, const int* in_sizes, int n_in,
                              void* d_out, int out_size)
{
    const float* q = (const float*)d_in[0];
    const float* k = (const float*)d_in[1];
    const float* v = (const float*)d_in[2];
    const float* W = (const float*)d_in[3];
    const float* b = (const float*)d_in[4];
    float* out = (float*)d_out;

    convert_w<<<DM * DM / 4 / 256, 256>>>(W);

    proj_kernel<<<dim3(8, 384), 512>>>(q, k, v, b);

    attn_kernel<<<MTOT, 256>>>();

    final_kernel<<<dim3(8, 128), 512>>>(b, out);
}